// round 1
// baseline (speedup 1.0000x reference)
#include <cuda_runtime.h>
#include <cuda_bf16.h>

// Sparse 3D conv: out[out_map[k,m]] += feats[in_map[k,m]] @ kernel[k]
// N=200000, K=27, M=50000, Cin=Cout=64, fp32.

#define KOFF   27
#define MPAIRS 50000
#define NVOX   200000
#define CIN    64
#define COUT   64
#define TILE_M 256
#define FSTRIDE 68   // 64 + 4 pad: conflict-free gather STS.128 and compute LDS

__global__ void spconv_zero_kernel(float4* __restrict__ out, int n4) {
    int i = blockIdx.x * blockDim.x + threadIdx.x;
    if (i < n4) out[i] = make_float4(0.f, 0.f, 0.f, 0.f);
}

__global__ __launch_bounds__(256, 2)
void spconv_kernel(const float* __restrict__ feats,
                   const float* __restrict__ kern,
                   const int*   __restrict__ in_map,
                   const int*   __restrict__ out_map,
                   float*       __restrict__ out)
{
    extern __shared__ float sh[];
    float* Wsh = sh;                      // 64*64 = 4096 floats (16 KB)
    float* Fsh = sh + CIN * COUT;         // TILE_M * FSTRIDE floats (68 KB)

    const int k   = blockIdx.y;
    const int m0  = blockIdx.x * TILE_M;
    const int tid = threadIdx.x;

    // ---- Stage W[k] (64x64) into smem, float4-coalesced ----
    {
        const float4* Wg = reinterpret_cast<const float4*>(kern + (size_t)k * CIN * COUT);
        float4* Ws4 = reinterpret_cast<float4*>(Wsh);
        #pragma unroll
        for (int idx = tid; idx < (CIN * COUT) / 4; idx += 256)
            Ws4[idx] = Wg[idx];
    }

    // ---- Gather 256 feature rows into smem ----
    // 16 threads per row (float4 each = 64 floats), 16 rows per sweep.
    {
        const int rlane = tid & 15;   // which 16B chunk of the row
        const int rgrp  = tid >> 4;   // which row in the sweep
        const int* im = in_map + (size_t)k * MPAIRS;
        #pragma unroll
        for (int r = rgrp; r < TILE_M; r += 16) {
            int m = m0 + r;
            float4 v = make_float4(0.f, 0.f, 0.f, 0.f);
            if (m < MPAIRS) {
                int row = im[m];
                v = *reinterpret_cast<const float4*>(feats + (size_t)row * CIN + rlane * 4);
            }
            *reinterpret_cast<float4*>(Fsh + r * FSTRIDE + rlane * 4) = v;
        }
    }
    __syncthreads();

    // ---- Register-tiled GEMM: each thread 8 pairs x 8 couts ----
    const int tx = tid & 7;    // cout group: couts [tx*8, tx*8+8)
    const int ty = tid >> 3;   // pair lane: pairs {ty + 32*q}

    float acc[8][8];
    #pragma unroll
    for (int q = 0; q < 8; ++q)
        #pragma unroll
        for (int j = 0; j < 8; ++j) acc[q][j] = 0.f;

    #pragma unroll 8
    for (int i = 0; i < CIN; ++i) {
        float4 w0 = *reinterpret_cast<const float4*>(Wsh + i * COUT + tx * 8);
        float4 w1 = *reinterpret_cast<const float4*>(Wsh + i * COUT + tx * 8 + 4);
        float wr[8] = {w0.x, w0.y, w0.z, w0.w, w1.x, w1.y, w1.z, w1.w};
        float fr[8];
        #pragma unroll
        for (int q = 0; q < 8; ++q)
            fr[q] = Fsh[(ty + 32 * q) * FSTRIDE + i];
        #pragma unroll
        for (int q = 0; q < 8; ++q)
            #pragma unroll
            for (int j = 0; j < 8; ++j)
                acc[q][j] = fmaf(fr[q], wr[j], acc[q][j]);
    }

    // ---- Scatter-add with vectorized global reductions ----
    {
        const int* om = out_map + (size_t)k * MPAIRS;
        #pragma unroll
        for (int q = 0; q < 8; ++q) {
            int m = m0 + ty + 32 * q;
            if (m < MPAIRS) {
                int orow = om[m];
                float* dst = out + (size_t)orow * COUT + tx * 8;
                asm volatile("red.global.add.v4.f32 [%0], {%1,%2,%3,%4};"
                             :: "l"(dst), "f"(acc[q][0]), "f"(acc[q][1]),
                                "f"(acc[q][2]), "f"(acc[q][3]) : "memory");
                asm volatile("red.global.add.v4.f32 [%0], {%1,%2,%3,%4};"
                             :: "l"(dst + 4), "f"(acc[q][4]), "f"(acc[q][5]),
                                "f"(acc[q][6]), "f"(acc[q][7]) : "memory");
            }
        }
    }
}

extern "C" void kernel_launch(void* const* d_in, const int* in_sizes, int n_in,
                              void* d_out, int out_size) {
    const float* feats  = (const float*)d_in[0];   // [N, 64]
    const float* kern   = (const float*)d_in[1];   // [27, 64, 64]
    const int*   in_map = (const int*)d_in[2];     // [27, 50000]
    const int*   out_map= (const int*)d_in[3];     // [27, 50000]
    float* out = (float*)d_out;                    // [N, 64]

    // Zero the (poisoned) output first.
    int n4 = NVOX * COUT / 4;
    spconv_zero_kernel<<<(n4 + 255) / 256, 256>>>((float4*)out, n4);

    // Main fused gather-GEMM-scatter.
    int smem_bytes = (CIN * COUT + TILE_M * FSTRIDE) * (int)sizeof(float);  // 84 KB
    cudaFuncSetAttribute(spconv_kernel,
                         cudaFuncAttributeMaxDynamicSharedMemorySize, smem_bytes);
    dim3 grid((MPAIRS + TILE_M - 1) / TILE_M, KOFF);
    spconv_kernel<<<grid, 256, smem_bytes>>>(feats, kern, in_map, out_map, out);
}

// round 3
// speedup vs baseline: 1.7679x; 1.7679x over previous
#include <cuda_runtime.h>
#include <cstdint>

// Sparse 3D conv via mma.sync tf32 (portable sm_80+ tensor path; tcgen05 PTX is
// rejected because the harness targets compute_103 without the 'a' suffix).
// out[out_map[k,m]] += feats[in_map[k,m]] @ kernel[k]
// N=200000, K=27, M=50000, Cin=Cout=64, fp32 in/out, tf32(RNA) MMA.

#define KOFF    27
#define MPAIRS  50000
#define NVOX    200000
#define CIN     64
#define COUT    64
#define TILE_M  256
#define FSTRIDE 68            // 64 + 4 pad -> conflict-free LDS for all fragments
#define SMEM_WORDS (TILE_M * FSTRIDE + COUT * FSTRIDE)   // A tile + B tile

__device__ __forceinline__ uint32_t f2tf32(float f) {
    uint32_t r;
    asm("cvt.rna.tf32.f32 %0, %1;" : "=r"(r) : "f"(f));
    return r;
}

__device__ __forceinline__ void mma_tf32(float c[4], const uint32_t a[4], const uint32_t b[2]) {
    asm volatile(
        "mma.sync.aligned.m16n8k8.row.col.f32.tf32.tf32.f32 "
        "{%0,%1,%2,%3}, {%4,%5,%6,%7}, {%8,%9}, {%0,%1,%2,%3};"
        : "+f"(c[0]), "+f"(c[1]), "+f"(c[2]), "+f"(c[3])
        : "r"(a[0]), "r"(a[1]), "r"(a[2]), "r"(a[3]), "r"(b[0]), "r"(b[1]));
}

__global__ void spconv_zero_kernel(float4* __restrict__ out, int n4) {
    int i = blockIdx.x * blockDim.x + threadIdx.x;
    if (i < n4) out[i] = make_float4(0.f, 0.f, 0.f, 0.f);
}

__global__ __launch_bounds__(256, 2)
void spconv_mma_kernel(const float* __restrict__ feats,
                       const float* __restrict__ kern,
                       const int*   __restrict__ in_map,
                       const int*   __restrict__ out_map,
                       float*       __restrict__ out)
{
    extern __shared__ uint32_t sh[];
    uint32_t* Ash = sh;                         // [TILE_M][FSTRIDE] tf32
    uint32_t* Bsh = sh + TILE_M * FSTRIDE;      // [COUT(perm)][FSTRIDE] tf32 (W^T, rows permuted)

    const int k   = blockIdx.y;
    const int m0  = blockIdx.x * TILE_M;
    const int tid = threadIdx.x;
    const int wid = tid >> 5;
    const int lid = tid & 31;

    // ---- Gather A: 256 rows x 64 cols, tf32-rounded ----
    {
        const int rlane = tid & 15;            // 16B chunk of the row
        const int rgrp  = tid >> 4;
        const int* im = in_map + (size_t)k * MPAIRS;
        #pragma unroll
        for (int r = rgrp; r < TILE_M; r += 16) {
            int m = m0 + r;
            uint4 u = make_uint4(0u, 0u, 0u, 0u);
            if (m < MPAIRS) {
                int row = im[m];
                float4 v = *reinterpret_cast<const float4*>(feats + (size_t)row * CIN + rlane * 4);
                u.x = f2tf32(v.x); u.y = f2tf32(v.y); u.z = f2tf32(v.z); u.w = f2tf32(v.w);
            }
            *reinterpret_cast<uint4*>(Ash + r * FSTRIDE + rlane * 4) = u;
        }
    }

    // ---- Stage B = W[k]^T with permuted cout rows ----
    // cout o -> (tile, j): P=o>>4, local=o&15, t=local>>2, r=local&3,
    //   tile = 2P + (r>>1), j = 2t + (r&1), pos = tile*8 + j.
    // This makes each thread's accum across a tile pair cover 4 contiguous couts.
    {
        const float* W = kern + (size_t)k * CIN * COUT;
        #pragma unroll
        for (int idx = tid; idx < CIN * COUT; idx += 256) {
            int i = idx >> 6;                  // cin
            int o = idx & 63;                  // cout (contiguous -> coalesced LDG)
            int P = o >> 4, local = o & 15;
            int t = local >> 2, r = local & 3;
            int pos = (2 * P + (r >> 1)) * 8 + 2 * t + (r & 1);
            Bsh[pos * FSTRIDE + i] = f2tf32(W[idx]);
        }
    }
    __syncthreads();

    // ---- Warp GEMM: rows [32*wid, 32*wid+32), all 64 couts ----
    const int g = lid >> 2;                    // group id (row within 8)
    const int t = lid & 3;                     // thread in group

    float acc[2][8][4];
    #pragma unroll
    for (int mt = 0; mt < 2; ++mt)
        #pragma unroll
        for (int nt = 0; nt < 8; ++nt)
            #pragma unroll
            for (int e = 0; e < 4; ++e) acc[mt][nt][e] = 0.f;

    const int mbase = wid * 32;
    #pragma unroll
    for (int s = 0; s < 8; ++s) {
        const int kc = s * 8;
        uint32_t bf[8][2];
        #pragma unroll
        for (int nt = 0; nt < 8; ++nt) {
            const uint32_t* bp = Bsh + (nt * 8 + g) * FSTRIDE + kc + t;
            bf[nt][0] = bp[0];
            bf[nt][1] = bp[4];
        }
        uint32_t af[2][4];
        #pragma unroll
        for (int mt = 0; mt < 2; ++mt) {
            const uint32_t* ap = Ash + (mbase + mt * 16 + g) * FSTRIDE + kc + t;
            af[mt][0] = ap[0];
            af[mt][1] = ap[8 * FSTRIDE];
            af[mt][2] = ap[4];
            af[mt][3] = ap[8 * FSTRIDE + 4];
        }
        #pragma unroll
        for (int mt = 0; mt < 2; ++mt)
            #pragma unroll
            for (int nt = 0; nt < 8; ++nt)
                mma_tf32(acc[mt][nt], af[mt], bf[nt]);
    }

    // ---- Scatter: vectorized global reductions, 4 contiguous couts per red ----
    {
        const int* om = out_map + (size_t)k * MPAIRS;
        #pragma unroll
        for (int mt = 0; mt < 2; ++mt) {
            #pragma unroll
            for (int half = 0; half < 2; ++half) {   // rows g and g+8
                int m = m0 + mbase + mt * 16 + g + half * 8;
                if (m < MPAIRS) {
                    int orow = om[m];
                    float* dst = out + (size_t)orow * COUT + t * 4;
                    #pragma unroll
                    for (int P = 0; P < 4; ++P) {
                        // couts 16P + 4t .. +3
                        asm volatile("red.global.add.v4.f32 [%0], {%1,%2,%3,%4};"
                                     :: "l"(dst + 16 * P),
                                        "f"(acc[mt][2 * P][half * 2]),
                                        "f"(acc[mt][2 * P][half * 2 + 1]),
                                        "f"(acc[mt][2 * P + 1][half * 2]),
                                        "f"(acc[mt][2 * P + 1][half * 2 + 1]) : "memory");
                    }
                }
            }
        }
    }
}

extern "C" void kernel_launch(void* const* d_in, const int* in_sizes, int n_in,
                              void* d_out, int out_size) {
    const float* feats   = (const float*)d_in[0];   // [N, 64]
    const float* kern    = (const float*)d_in[1];   // [27, 64, 64]
    const int*   in_map  = (const int*)d_in[2];     // [27, 50000]
    const int*   out_map = (const int*)d_in[3];     // [27, 50000]
    float* out = (float*)d_out;                     // [N, 64]

    int n4 = NVOX * COUT / 4;
    spconv_zero_kernel<<<(n4 + 255) / 256, 256>>>((float4*)out, n4);

    int smem_bytes = SMEM_WORDS * (int)sizeof(uint32_t);   // 87040
    cudaFuncSetAttribute(spconv_mma_kernel,
                         cudaFuncAttributeMaxDynamicSharedMemorySize, smem_bytes);
    dim3 grid((MPAIRS + TILE_M - 1) / TILE_M, KOFF);
    spconv_mma_kernel<<<grid, 256, smem_bytes>>>(feats, kern, in_map, out_map, out);
}